// round 14
// baseline (speedup 1.0000x reference)
// MoE top-2, grouped-GEMM formulation for GB300 (sm_103a).
// Round 13: occupancy push — CTA tile 128x64 (BN 128->64), warp tile 32x32,
//           stage smem 40960->30720 B => 3 CTAs/SM (24 warps, occ 24%->37.5%).
//           ncu R13 showed tensor=56%, issue=24%, occ=24%, DRAM=4%: latency-
//           bound, not pipe-bound. Same math order => bit-identical rel_err.
//   kS: merged zero(out,counts) + pre-split x / w_fc / w_proj into bf16 hi/lo
//   k1: router (logits, top-2, pair softmax, atomic append to expert lists)
//   k2: 8-way prefix scan of counts -> compact hmid slots
//   k3: grouped GEMM1  hmid = gelu(x_gather @ w_fc^T + b_fc)   [3x bf16 mma]
//   k4: grouped GEMM2  out += gate * (hmid @ w_proj^T + b_proj) [3x bf16 mma, atomicAdd]
#include <cuda_runtime.h>
#include <cuda_bf16.h>
#include <cstdint>

#define DEVFN __device__ __forceinline__

constexpr int H_ = 1024;
constexpr int I_ = 2048;
constexpr int E_ = 8;
constexpr int T_ = 16384;           // B*S = 4*4096
constexpr int NPAIR = 2 * T_;       // every token routes to exactly 2 experts

constexpr int BM = 128, BN = 64, BK = 32;
constexpr int PB = 40;                         // bf16 elems per smem row (80 B pitch)
constexpr int PLANE_A = BM * PB * 2;           // 10240 B
constexpr int PLANE_B = BN * PB * 2;           // 5120 B
constexpr int STAGE_BYTES = 2 * PLANE_A + 2 * PLANE_B;   // 30720 B
constexpr int SMEM_TOTAL = 2 * STAGE_BYTES;              // 61440 B -> 3 CTAs/SM

// ---------------- scratch (device globals; no runtime allocation) ----------------
__device__ int   g_counts[E_];
__device__ int   g_offsets[E_];
__device__ int   g_tok[E_ * T_];
__device__ float g_gate[E_ * T_];

// bf16 hi/lo planes
__device__ __nv_bfloat16 g_xhi[T_ * H_],          g_xlo[T_ * H_];
__device__ __nv_bfloat16 g_wfchi[E_ * I_ * H_],   g_wfclo[E_ * I_ * H_];
__device__ __nv_bfloat16 g_wprojhi[E_ * H_ * I_], g_wprojlo[E_ * H_ * I_];
__device__ __nv_bfloat16 g_hmidhi[(long long)NPAIR * I_];
__device__ __nv_bfloat16 g_hmidlo[(long long)NPAIR * I_];

// ---------------- small helpers ----------------
DEVFN void cp_async16(uint32_t smem_addr, const void* gptr) {
    asm volatile("cp.async.cg.shared.global [%0], [%1], 16;\n"
                 :: "r"(smem_addr), "l"(gptr));
}
DEVFN void cp_commit() { asm volatile("cp.async.commit_group;\n"); }
template <int N> DEVFN void cp_wait() {
    asm volatile("cp.async.wait_group %0;\n" :: "n"(N));
}

DEVFN void mma_bf16(float c[4], const uint32_t a[4], uint32_t b0, uint32_t b1) {
    asm volatile(
        "mma.sync.aligned.m16n8k16.row.col.f32.bf16.bf16.f32 "
        "{%0,%1,%2,%3}, {%4,%5,%6,%7}, {%8,%9}, {%0,%1,%2,%3};\n"
        : "+f"(c[0]), "+f"(c[1]), "+f"(c[2]), "+f"(c[3])
        : "r"(a[0]), "r"(a[1]), "r"(a[2]), "r"(a[3]), "r"(b0), "r"(b1));
}

DEVFN float gelu_f(float v) {
    return 0.5f * v * (1.0f + erff(v * 0.70710678118654752440f));
}

DEVFN uint32_t pack2(__nv_bfloat16 a, __nv_bfloat16 b) {
    return (uint32_t)__bfloat16_as_ushort(a) | ((uint32_t)__bfloat16_as_ushort(b) << 16);
}
DEVFN void split2(float v0, float v1, uint32_t& hi, uint32_t& lo) {
    const __nv_bfloat16 h0 = __float2bfloat16_rn(v0);
    const __nv_bfloat16 h1 = __float2bfloat16_rn(v1);
    const __nv_bfloat16 l0 = __float2bfloat16_rn(v0 - __bfloat162float(h0));
    const __nv_bfloat16 l1 = __float2bfloat16_rn(v1 - __bfloat162float(h1));
    hi = pack2(h0, h1);
    lo = pack2(l0, l1);
}

// per-stage compute: 8 warps as 4(M)x2(N), warp tile 32x32, m16n8k16,
// 3-term bf16 split (per-acc term order hh,lh,hl unchanged -> bit-identical).
DEVFN void compute_stage(const __nv_bfloat16* __restrict__ Ah, const __nv_bfloat16* __restrict__ Al,
                         const __nv_bfloat16* __restrict__ Bh, const __nv_bfloat16* __restrict__ Bl,
                         int g, int tg, int wm, int wn, float acc[2][4][4]) {
#pragma unroll
    for (int ks = 0; ks < 2; ++ks) {
        const int kc = ks * 16 + 2 * tg;
        uint32_t ah[2][4], al[2][4];
#pragma unroll
        for (int mi = 0; mi < 2; ++mi) {
            const int o = (wm * 32 + mi * 16 + g) * PB + kc;
            ah[mi][0] = *(const uint32_t*)(Ah + o);
            ah[mi][1] = *(const uint32_t*)(Ah + o + 8 * PB);
            ah[mi][2] = *(const uint32_t*)(Ah + o + 8);
            ah[mi][3] = *(const uint32_t*)(Ah + o + 8 * PB + 8);
            al[mi][0] = *(const uint32_t*)(Al + o);
            al[mi][1] = *(const uint32_t*)(Al + o + 8 * PB);
            al[mi][2] = *(const uint32_t*)(Al + o + 8);
            al[mi][3] = *(const uint32_t*)(Al + o + 8 * PB + 8);
        }
#pragma unroll
        for (int ni = 0; ni < 4; ++ni) {
            const int o = (wn * 32 + ni * 8 + g) * PB + kc;
            const uint32_t bh0 = *(const uint32_t*)(Bh + o);
            const uint32_t bh1 = *(const uint32_t*)(Bh + o + 8);
            const uint32_t bl0 = *(const uint32_t*)(Bl + o);
            const uint32_t bl1 = *(const uint32_t*)(Bl + o + 8);
#pragma unroll
            for (int mi = 0; mi < 2; ++mi)     // hi*hi
                mma_bf16(acc[mi][ni], ah[mi], bh0, bh1);
#pragma unroll
            for (int mi = 0; mi < 2; ++mi)     // lo*hi
                mma_bf16(acc[mi][ni], al[mi], bh0, bh1);
#pragma unroll
            for (int mi = 0; mi < 2; ++mi)     // hi*lo
                mma_bf16(acc[mi][ni], ah[mi], bl0, bl1);
        }
    }
}

// stage loader: thread owns A rows (r, r+64) and B row r, chunk cc (16B); 6 cp.async
DEVFN void load_tiles(uint32_t smu, int stage,
                      const __nv_bfloat16* const aHi[2], const __nv_bfloat16* const aLo[2],
                      const __nv_bfloat16* bHi, const __nv_bfloat16* bLo,
                      int k0, int r, int cc) {
    const uint32_t sb = smu + (uint32_t)(stage * STAGE_BYTES);
#pragma unroll
    for (int p = 0; p < 2; ++p) {
        const uint32_t so = (uint32_t)((r + p * 64) * 80 + cc * 16);
        cp_async16(sb + so, aHi[p] + k0);
        cp_async16(sb + PLANE_A + so, aLo[p] + k0);
    }
    const uint32_t sob = (uint32_t)(r * 80 + cc * 16);
    cp_async16(sb + 2 * PLANE_A + sob, bHi + k0);
    cp_async16(sb + 2 * PLANE_A + PLANE_B + sob, bLo + k0);
}

// ---------------- kS: merged zero + split of x / w_fc / w_proj ----------------
__global__ void split_all_kernel(const float4* __restrict__ x,
                                 const float4* __restrict__ wfc,
                                 const float4* __restrict__ wproj,
                                 uint2* __restrict__ xhi,  uint2* __restrict__ xlo,
                                 uint2* __restrict__ fchi, uint2* __restrict__ fclo,
                                 uint2* __restrict__ pjhi, uint2* __restrict__ pjlo,
                                 float4* __restrict__ out) {
    constexpr size_t N1 = (size_t)T_ * H_ / 4;       // x float4 count == out float4 count
    constexpr size_t N2 = (size_t)E_ * I_ * H_ / 4;
    size_t i = (size_t)blockIdx.x * 256 + threadIdx.x;
    if (blockIdx.x == 0 && threadIdx.x < E_) g_counts[threadIdx.x] = 0;
    const float4* in; uint2 *hi, *lo;
    if (i < N1)            { in = x;     hi = xhi;  lo = xlo;
                             out[i] = make_float4(0.f, 0.f, 0.f, 0.f); }
    else if (i < N1 + N2)  { i -= N1;      in = wfc;   hi = fchi; lo = fclo; }
    else                   { i -= N1 + N2; in = wproj; hi = pjhi; lo = pjlo; }
    const float4 v = in[i];
    uint2 h, l;
    split2(v.x, v.y, h.x, l.x);
    split2(v.z, v.w, h.y, l.y);
    hi[i] = h;
    lo[i] = l;
}

// ---------------- k1: router ----------------
__global__ void route_kernel(const float* __restrict__ x,
                             const float* __restrict__ w_gate) {
    __shared__ float4 sWg[E_ * (H_ / 4)];   // 32 KB
    const int tid = threadIdx.x;
    for (int i = tid; i < E_ * (H_ / 4); i += 128)
        sWg[i] = ((const float4*)w_gate)[i];
    __syncthreads();

    const int t = blockIdx.x * 128 + tid;
    const float4* xr = (const float4*)(x + (size_t)t * H_);
    float acc[E_];
#pragma unroll
    for (int e = 0; e < E_; ++e) acc[e] = 0.f;

    for (int i = 0; i < H_ / 4; ++i) {
        const float4 v = xr[i];
#pragma unroll
        for (int e = 0; e < E_; ++e) {
            const float4 w = sWg[e * (H_ / 4) + i];   // broadcast LDS
            acc[e] = fmaf(v.x, w.x, fmaf(v.y, w.y, fmaf(v.z, w.z, fmaf(v.w, w.w, acc[e]))));
        }
    }

    // top-2 (first-index wins on ties, matching lax.top_k)
    int e1 = 0; float v1 = acc[0];
#pragma unroll
    for (int e = 1; e < E_; ++e) if (acc[e] > v1) { v1 = acc[e]; e1 = e; }
    int e2 = -1; float v2 = -3.4e38f;
#pragma unroll
    for (int e = 0; e < E_; ++e) if (e != e1 && acc[e] > v2) { v2 = acc[e]; e2 = e; }

    const float d  = expf(v2 - v1);          // <= 1
    const float iv = 1.0f / (1.0f + d);
    const float g1 = iv, g2 = d * iv;        // softmax over [v1, v2]

    int p1 = atomicAdd(&g_counts[e1], 1);
    g_tok[e1 * T_ + p1] = t;  g_gate[e1 * T_ + p1] = g1;
    int p2 = atomicAdd(&g_counts[e2], 1);
    g_tok[e2 * T_ + p2] = t;  g_gate[e2 * T_ + p2] = g2;
}

// ---------------- k2: exclusive scan of 8 counts ----------------
__global__ void scan_kernel() {
    int o = 0;
#pragma unroll
    for (int e = 0; e < E_; ++e) { g_offsets[e] = o; o += g_counts[e]; }
}

// ---------------- k3: grouped GEMM1  hmid = gelu(x_gather @ w_fc^T + b_fc) ----------------
__global__ __launch_bounds__(256, 3)
void gemm_fc_kernel(const float* __restrict__ b_fc) {
    const int e    = blockIdx.z;
    const int tile = blockIdx.y;
    const int cnt  = g_counts[e];
    if (tile * BM >= cnt) return;
    const int rem  = min(cnt - tile * BM, BM);
    const int hoff = g_offsets[e];
    const int n0   = blockIdx.x * BN;

    extern __shared__ __nv_bfloat16 sm[];
    __shared__ int tok_s[BM];

    const int tid = threadIdx.x;
    if (tid < BM) {
        const int rr = tile * BM + tid;
        tok_s[tid] = g_tok[e * T_ + min(rr, cnt - 1)];   // clamp invalid rows
    }
    __syncthreads();

    const int cc = tid & 3;          // 16B chunk within BK=32 (8 bf16 per chunk)
    const int r  = tid >> 2;         // 0..63
    const __nv_bfloat16* aHi[2]; const __nv_bfloat16* aLo[2];
#pragma unroll
    for (int p = 0; p < 2; ++p) {
        const size_t ao = (size_t)tok_s[r + p * 64] * H_ + cc * 8;
        aHi[p] = g_xhi + ao;    aLo[p] = g_xlo + ao;
    }
    const size_t bo = ((size_t)e * I_ + n0 + r) * H_ + cc * 8;
    const __nv_bfloat16* bHi = g_wfchi + bo;
    const __nv_bfloat16* bLo = g_wfclo + bo;
    const uint32_t smu = (uint32_t)__cvta_generic_to_shared(sm);

    const int lane = tid & 31, warp = tid >> 5;
    const int g = lane >> 2, tg = lane & 3;
    const int wm = warp >> 1, wn = warp & 1;   // 4(M) x 2(N)

    float acc[2][4][4];
#pragma unroll
    for (int mi = 0; mi < 2; ++mi)
#pragma unroll
        for (int ni = 0; ni < 4; ++ni)
#pragma unroll
            for (int q = 0; q < 4; ++q) acc[mi][ni][q] = 0.f;

    constexpr int KT = H_ / BK;   // 32
    load_tiles(smu, 0, aHi, aLo, bHi, bLo, 0, r, cc);
    cp_commit();
    for (int kt = 0; kt < KT; ++kt) {
        cp_wait<0>();
        __syncthreads();
        if (kt + 1 < KT) {
            load_tiles(smu, (kt + 1) & 1, aHi, aLo, bHi, bLo, (kt + 1) * BK, r, cc);
            cp_commit();
        }
        const __nv_bfloat16* st = sm + (size_t)(kt & 1) * (STAGE_BYTES / 2);
        compute_stage(st, st + PLANE_A / 2, st + PLANE_A, st + PLANE_A + PLANE_B / 2,
                      g, tg, wm, wn, acc);
    }

    // epilogue: bias + exact-erf gelu, split-store to compact hmid hi/lo planes
    const float* bf = b_fc + e * I_;
    const size_t base = (size_t)(hoff + tile * BM);
#pragma unroll
    for (int mi = 0; mi < 2; ++mi) {
        const int rr = wm * 32 + mi * 16 + g;
#pragma unroll
        for (int ni = 0; ni < 4; ++ni) {
            const int colg = n0 + wn * 32 + ni * 8 + 2 * tg;
            if (rr < rem) {
                const size_t o = (base + rr) * I_ + colg;
                uint32_t h, l;
                split2(gelu_f(acc[mi][ni][0] + bf[colg]),
                       gelu_f(acc[mi][ni][1] + bf[colg + 1]), h, l);
                *(uint32_t*)(g_hmidhi + o) = h;
                *(uint32_t*)(g_hmidlo + o) = l;
            }
            if (rr + 8 < rem) {
                const size_t o = (base + rr + 8) * I_ + colg;
                uint32_t h, l;
                split2(gelu_f(acc[mi][ni][2] + bf[colg]),
                       gelu_f(acc[mi][ni][3] + bf[colg + 1]), h, l);
                *(uint32_t*)(g_hmidhi + o) = h;
                *(uint32_t*)(g_hmidlo + o) = l;
            }
        }
    }
}

// ---------------- k4: grouped GEMM2  out += gate * (hmid @ w_proj^T + b_proj) ----------------
__global__ __launch_bounds__(256, 3)
void gemm_proj_kernel(const float* __restrict__ b_proj, float* __restrict__ out) {
    const int e    = blockIdx.z;
    const int tile = blockIdx.y;
    const int cnt  = g_counts[e];
    if (tile * BM >= cnt) return;
    const int rem  = min(cnt - tile * BM, BM);
    const int hoff = g_offsets[e];
    const int n0   = blockIdx.x * BN;

    extern __shared__ __nv_bfloat16 sm[];
    __shared__ int   tok_s[BM];
    __shared__ float gate_s[BM];

    const int tid = threadIdx.x;
    if (tid < BM) {
        const int rr  = tile * BM + tid;
        const int idx = e * T_ + min(rr, cnt - 1);
        tok_s[tid]  = g_tok[idx];
        gate_s[tid] = g_gate[idx];
    }
    __syncthreads();

    const int cc = tid & 3;
    const int r  = tid >> 2;
    const __nv_bfloat16* aHi[2]; const __nv_bfloat16* aLo[2];
#pragma unroll
    for (int p = 0; p < 2; ++p) {
        const int slot = min(hoff + tile * BM + r + p * 64, NPAIR - 1);
        const size_t ao = (size_t)slot * I_ + cc * 8;
        aHi[p] = g_hmidhi + ao;   aLo[p] = g_hmidlo + ao;
    }
    const size_t bo = ((size_t)e * H_ + n0 + r) * I_ + cc * 8;
    const __nv_bfloat16* bHi = g_wprojhi + bo;
    const __nv_bfloat16* bLo = g_wprojlo + bo;
    const uint32_t smu = (uint32_t)__cvta_generic_to_shared(sm);

    const int lane = tid & 31, warp = tid >> 5;
    const int g = lane >> 2, tg = lane & 3;
    const int wm = warp >> 1, wn = warp & 1;

    float acc[2][4][4];
#pragma unroll
    for (int mi = 0; mi < 2; ++mi)
#pragma unroll
        for (int ni = 0; ni < 4; ++ni)
#pragma unroll
            for (int q = 0; q < 4; ++q) acc[mi][ni][q] = 0.f;

    constexpr int KT = I_ / BK;   // 64
    load_tiles(smu, 0, aHi, aLo, bHi, bLo, 0, r, cc);
    cp_commit();
    for (int kt = 0; kt < KT; ++kt) {
        cp_wait<0>();
        __syncthreads();
        if (kt + 1 < KT) {
            load_tiles(smu, (kt + 1) & 1, aHi, aLo, bHi, bLo, (kt + 1) * BK, r, cc);
            cp_commit();
        }
        const __nv_bfloat16* st = sm + (size_t)(kt & 1) * (STAGE_BYTES / 2);
        compute_stage(st, st + PLANE_A / 2, st + PLANE_A, st + PLANE_A + PLANE_B / 2,
                      g, tg, wm, wn, acc);
    }

    // epilogue: bias, gate scale, scatter-add into out
    const float* bp = b_proj + e * H_;
#pragma unroll
    for (int mi = 0; mi < 2; ++mi) {
        const int rr = wm * 32 + mi * 16 + g;
#pragma unroll
        for (int ni = 0; ni < 4; ++ni) {
            const int colg = n0 + wn * 32 + ni * 8 + 2 * tg;
            if (rr < rem) {
                const int tk = tok_s[rr];
                const float gv = gate_s[rr];
                atomicAdd(out + (size_t)tk * H_ + colg,     gv * (acc[mi][ni][0] + bp[colg]));
                atomicAdd(out + (size_t)tk * H_ + colg + 1, gv * (acc[mi][ni][1] + bp[colg + 1]));
            }
            if (rr + 8 < rem) {
                const int tk = tok_s[rr + 8];
                const float gv = gate_s[rr + 8];
                atomicAdd(out + (size_t)tk * H_ + colg,     gv * (acc[mi][ni][2] + bp[colg]));
                atomicAdd(out + (size_t)tk * H_ + colg + 1, gv * (acc[mi][ni][3] + bp[colg + 1]));
            }
        }
    }
}

// ---------------- launch ----------------
extern "C" void kernel_launch(void* const* d_in, const int* in_sizes, int n_in,
                              void* d_out, int out_size) {
    const float* x      = (const float*)d_in[0];
    const float* w_gate = (const float*)d_in[1];
    const float* w_fc   = (const float*)d_in[2];
    const float* b_fc   = (const float*)d_in[3];
    const float* w_proj = (const float*)d_in[4];
    const float* b_proj = (const float*)d_in[5];
    float* out = (float*)d_out;

    cudaFuncSetAttribute(gemm_fc_kernel,   cudaFuncAttributeMaxDynamicSharedMemorySize, SMEM_TOTAL);
    cudaFuncSetAttribute(gemm_proj_kernel, cudaFuncAttributeMaxDynamicSharedMemorySize, SMEM_TOTAL);

    static uint2* p_xhi = nullptr;
    static uint2* p_xlo, *p_wfchi, *p_wfclo, *p_wprojhi, *p_wprojlo;
    if (!p_xhi) {
        void* p;
        cudaGetSymbolAddress(&p, g_xhi);     p_xhi     = (uint2*)p;
        cudaGetSymbolAddress(&p, g_xlo);     p_xlo     = (uint2*)p;
        cudaGetSymbolAddress(&p, g_wfchi);   p_wfchi   = (uint2*)p;
        cudaGetSymbolAddress(&p, g_wfclo);   p_wfclo   = (uint2*)p;
        cudaGetSymbolAddress(&p, g_wprojhi); p_wprojhi = (uint2*)p;
        cudaGetSymbolAddress(&p, g_wprojlo); p_wprojlo = (uint2*)p;
    }

    constexpr int SPLIT_BLOCKS = (T_ * H_ + E_ * I_ * H_ + E_ * H_ * I_) / (4 * 256);

    // launch order: split_all(0) route(1) scan(2) gemm_fc(3) gemm_proj(4)
    // -> ncu's fixed capture slot (launch index 3) lands on gemm_fc_kernel.
    split_all_kernel<<<SPLIT_BLOCKS, 256>>>((const float4*)x, (const float4*)w_fc,
                                            (const float4*)w_proj,
                                            p_xhi, p_xlo, p_wfchi, p_wfclo,
                                            p_wprojhi, p_wprojlo, (float4*)out);
    route_kernel<<<T_ / 128, 128>>>(x, w_gate);
    scan_kernel<<<1, 1>>>();
    gemm_fc_kernel<<<dim3(I_ / BN, T_ / BM, E_), 256, SMEM_TOTAL>>>(b_fc);
    gemm_proj_kernel<<<dim3(H_ / BN, T_ / BM, E_), 256, SMEM_TOTAL>>>(b_proj, out);
}

// round 15
// speedup vs baseline: 1.5302x; 1.5302x over previous
// MoE top-2, grouped-GEMM formulation for GB300 (sm_103a).
// Round 14: fp16 2-term split — planes in fp16 (hi err 2^-12 vs bf16 2^-9),
//           drop the ah*bl term entirely (B carries NO lo plane).
//           MMA count/warp-stage 96 -> 64. Config reverted to best-known R12
//           (BM=128/BN=128/BK=32, 2-stage, single barrier, scalar LDS).
//           Calibrated error model: tf32 dropped ~2^-10 -> 1.62e-3 measured;
//           here dropped ~2^-12 -> predicted ~4e-4 < 1e-3.
//   kS: merged zero(out,counts) + split x (hi/lo) + w_fc/w_proj (hi only)
//   k1: router (logits, top-2, pair softmax, atomic append to expert lists)
//   k2: 8-way prefix scan of counts -> compact hmid slots
//   k3: grouped GEMM1  hmid = gelu(x_gather @ w_fc^T + b_fc)   [2x fp16 mma]
//   k4: grouped GEMM2  out += gate * (hmid @ w_proj^T + b_proj) [2x fp16 mma, atomicAdd]
#include <cuda_runtime.h>
#include <cuda_fp16.h>
#include <cstdint>

#define DEVFN __device__ __forceinline__

constexpr int H_ = 1024;
constexpr int I_ = 2048;
constexpr int E_ = 8;
constexpr int T_ = 16384;           // B*S = 4*4096
constexpr int NPAIR = 2 * T_;       // every token routes to exactly 2 experts

constexpr int BM = 128, BN = 128, BK = 32;
constexpr int PB = 40;                         // fp16 elems per smem row (80 B pitch)
constexpr int PLANE_BYTES = BM * PB * 2;       // 10240 B
constexpr int STAGE_BYTES = 3 * PLANE_BYTES;   // Ahi, Alo, Bhi = 30720 B
constexpr int SMEM_TOTAL = 2 * STAGE_BYTES;    // 61440 B

// ---------------- scratch (device globals; no runtime allocation) ----------------
__device__ int   g_counts[E_];
__device__ int   g_offsets[E_];
__device__ int   g_tok[E_ * T_];
__device__ float g_gate[E_ * T_];

// fp16 planes: A-side operands carry hi+lo, B-side (weights) hi only
__device__ __half g_xhi[T_ * H_],        g_xlo[T_ * H_];
__device__ __half g_wfchi[E_ * I_ * H_];
__device__ __half g_wprojhi[E_ * H_ * I_];
__device__ __half g_hmidhi[(long long)NPAIR * I_];
__device__ __half g_hmidlo[(long long)NPAIR * I_];

// ---------------- small helpers ----------------
DEVFN void cp_async16(uint32_t smem_addr, const void* gptr) {
    asm volatile("cp.async.cg.shared.global [%0], [%1], 16;\n"
                 :: "r"(smem_addr), "l"(gptr));
}
DEVFN void cp_commit() { asm volatile("cp.async.commit_group;\n"); }
template <int N> DEVFN void cp_wait() {
    asm volatile("cp.async.wait_group %0;\n" :: "n"(N));
}

DEVFN void mma_f16(float c[4], const uint32_t a[4], uint32_t b0, uint32_t b1) {
    asm volatile(
        "mma.sync.aligned.m16n8k16.row.col.f32.f16.f16.f32 "
        "{%0,%1,%2,%3}, {%4,%5,%6,%7}, {%8,%9}, {%0,%1,%2,%3};\n"
        : "+f"(c[0]), "+f"(c[1]), "+f"(c[2]), "+f"(c[3])
        : "r"(a[0]), "r"(a[1]), "r"(a[2]), "r"(a[3]), "r"(b0), "r"(b1));
}

DEVFN float gelu_f(float v) {
    return 0.5f * v * (1.0f + erff(v * 0.70710678118654752440f));
}

DEVFN uint32_t pack2h(__half a, __half b) {
    return (uint32_t)__half_as_ushort(a) | ((uint32_t)__half_as_ushort(b) << 16);
}
// split pair of floats into packed fp16 hi and lo words
DEVFN void split2h(float v0, float v1, uint32_t& hi, uint32_t& lo) {
    const __half h0 = __float2half_rn(v0);
    const __half h1 = __float2half_rn(v1);
    const __half l0 = __float2half_rn(v0 - __half2float(h0));
    const __half l1 = __float2half_rn(v1 - __half2float(h1));
    hi = pack2h(h0, h1);
    lo = pack2h(l0, l1);
}
DEVFN uint32_t hi2h(float v0, float v1) {
    return pack2h(__float2half_rn(v0), __float2half_rn(v1));
}

// per-stage compute: 8 warps as 2(M)x4(N), warp tile 64x32, m16n8k16,
// 2-term fp16 split: acc += ah*bh; acc += al*bh   (ah*bl dropped, ~2^-12)
DEVFN void compute_stage(const __half* __restrict__ Ah, const __half* __restrict__ Al,
                         const __half* __restrict__ Bh,
                         int g, int tg, int wm, int wn, float acc[4][4][4]) {
#pragma unroll
    for (int ks = 0; ks < 2; ++ks) {
        const int kc = ks * 16 + 2 * tg;
        uint32_t ah[4][4], al[4][4];
#pragma unroll
        for (int mi = 0; mi < 4; ++mi) {
            const int o = (wm * 64 + mi * 16 + g) * PB + kc;
            ah[mi][0] = *(const uint32_t*)(Ah + o);
            ah[mi][1] = *(const uint32_t*)(Ah + o + 8 * PB);
            ah[mi][2] = *(const uint32_t*)(Ah + o + 8);
            ah[mi][3] = *(const uint32_t*)(Ah + o + 8 * PB + 8);
            al[mi][0] = *(const uint32_t*)(Al + o);
            al[mi][1] = *(const uint32_t*)(Al + o + 8 * PB);
            al[mi][2] = *(const uint32_t*)(Al + o + 8);
            al[mi][3] = *(const uint32_t*)(Al + o + 8 * PB + 8);
        }
#pragma unroll
        for (int ni = 0; ni < 4; ++ni) {
            const int o = (wn * 32 + ni * 8 + g) * PB + kc;
            const uint32_t bh0 = *(const uint32_t*)(Bh + o);
            const uint32_t bh1 = *(const uint32_t*)(Bh + o + 8);
#pragma unroll
            for (int mi = 0; mi < 4; ++mi)     // hi*hi
                mma_f16(acc[mi][ni], ah[mi], bh0, bh1);
#pragma unroll
            for (int mi = 0; mi < 4; ++mi)     // lo*hi
                mma_f16(acc[mi][ni], al[mi], bh0, bh1);
        }
    }
}

// stage loader: thread owns rows (r, r+64) of the 3 planes, chunk cc (16B); 6 cp.async
DEVFN void load_tiles(uint32_t smu, int stage,
                      const __half* const aHi[2], const __half* const aLo[2],
                      const __half* const bHi[2],
                      int k0, int r, int cc) {
    const uint32_t sb = smu + (uint32_t)(stage * STAGE_BYTES);
#pragma unroll
    for (int p = 0; p < 2; ++p) {
        const uint32_t so = (uint32_t)((r + p * 64) * 80 + cc * 16);
        cp_async16(sb + so, aHi[p] + k0);
        cp_async16(sb + PLANE_BYTES + so, aLo[p] + k0);
        cp_async16(sb + 2 * PLANE_BYTES + so, bHi[p] + k0);
    }
}

// ---------------- kS: merged zero + split ----------------
__global__ void split_all_kernel(const float4* __restrict__ x,
                                 const float4* __restrict__ wfc,
                                 const float4* __restrict__ wproj,
                                 uint2* __restrict__ xhi, uint2* __restrict__ xlo,
                                 uint2* __restrict__ fchi, uint2* __restrict__ pjhi,
                                 float4* __restrict__ out) {
    constexpr size_t N1 = (size_t)T_ * H_ / 4;
    constexpr size_t N2 = (size_t)E_ * I_ * H_ / 4;
    size_t i = (size_t)blockIdx.x * 256 + threadIdx.x;
    if (blockIdx.x == 0 && threadIdx.x < E_) g_counts[threadIdx.x] = 0;
    if (i < N1) {
        out[i] = make_float4(0.f, 0.f, 0.f, 0.f);
        const float4 v = x[i];
        uint2 h, l;
        split2h(v.x, v.y, h.x, l.x);
        split2h(v.z, v.w, h.y, l.y);
        xhi[i] = h;
        xlo[i] = l;
    } else {
        uint2* hi;
        const float4* in;
        if (i < N1 + N2) { i -= N1;      in = wfc;   hi = fchi; }
        else             { i -= N1 + N2; in = wproj; hi = pjhi; }
        const float4 v = in[i];
        hi[i] = make_uint2(hi2h(v.x, v.y), hi2h(v.z, v.w));
    }
}

// ---------------- k1: router ----------------
__global__ void route_kernel(const float* __restrict__ x,
                             const float* __restrict__ w_gate) {
    __shared__ float4 sWg[E_ * (H_ / 4)];   // 32 KB
    const int tid = threadIdx.x;
    for (int i = tid; i < E_ * (H_ / 4); i += 128)
        sWg[i] = ((const float4*)w_gate)[i];
    __syncthreads();

    const int t = blockIdx.x * 128 + tid;
    const float4* xr = (const float4*)(x + (size_t)t * H_);
    float acc[E_];
#pragma unroll
    for (int e = 0; e < E_; ++e) acc[e] = 0.f;

    for (int i = 0; i < H_ / 4; ++i) {
        const float4 v = xr[i];
#pragma unroll
        for (int e = 0; e < E_; ++e) {
            const float4 w = sWg[e * (H_ / 4) + i];   // broadcast LDS
            acc[e] = fmaf(v.x, w.x, fmaf(v.y, w.y, fmaf(v.z, w.z, fmaf(v.w, w.w, acc[e]))));
        }
    }

    // top-2 (first-index wins on ties, matching lax.top_k)
    int e1 = 0; float v1 = acc[0];
#pragma unroll
    for (int e = 1; e < E_; ++e) if (acc[e] > v1) { v1 = acc[e]; e1 = e; }
    int e2 = -1; float v2 = -3.4e38f;
#pragma unroll
    for (int e = 0; e < E_; ++e) if (e != e1 && acc[e] > v2) { v2 = acc[e]; e2 = e; }

    const float d  = expf(v2 - v1);          // <= 1
    const float iv = 1.0f / (1.0f + d);
    const float g1 = iv, g2 = d * iv;        // softmax over [v1, v2]

    int p1 = atomicAdd(&g_counts[e1], 1);
    g_tok[e1 * T_ + p1] = t;  g_gate[e1 * T_ + p1] = g1;
    int p2 = atomicAdd(&g_counts[e2], 1);
    g_tok[e2 * T_ + p2] = t;  g_gate[e2 * T_ + p2] = g2;
}

// ---------------- k2: exclusive scan of 8 counts ----------------
__global__ void scan_kernel() {
    int o = 0;
#pragma unroll
    for (int e = 0; e < E_; ++e) { g_offsets[e] = o; o += g_counts[e]; }
}

// ---------------- k3: grouped GEMM1  hmid = gelu(x_gather @ w_fc^T + b_fc) ----------------
__global__ __launch_bounds__(256, 2)
void gemm_fc_kernel(const float* __restrict__ b_fc) {
    const int e    = blockIdx.z;
    const int tile = blockIdx.y;
    const int cnt  = g_counts[e];
    if (tile * BM >= cnt) return;
    const int rem  = min(cnt - tile * BM, BM);
    const int hoff = g_offsets[e];
    const int n0   = blockIdx.x * BN;

    extern __shared__ __half sm[];
    __shared__ int tok_s[BM];

    const int tid = threadIdx.x;
    if (tid < BM) {
        const int rr = tile * BM + tid;
        tok_s[tid] = g_tok[e * T_ + min(rr, cnt - 1)];   // clamp invalid rows
    }
    __syncthreads();

    const int cc = tid & 3;          // 16B chunk within BK=32 (8 fp16 per chunk)
    const int r  = tid >> 2;         // 0..63; rows r and r+64
    const __half* aHi[2]; const __half* aLo[2]; const __half* bHi[2];
#pragma unroll
    for (int p = 0; p < 2; ++p) {
        const int row = r + p * 64;
        const size_t ao = (size_t)tok_s[row] * H_ + cc * 8;
        const size_t bo = ((size_t)e * I_ + n0 + row) * H_ + cc * 8;
        aHi[p] = g_xhi + ao;    aLo[p] = g_xlo + ao;
        bHi[p] = g_wfchi + bo;
    }
    const uint32_t smu = (uint32_t)__cvta_generic_to_shared(sm);

    const int lane = tid & 31, warp = tid >> 5;
    const int g = lane >> 2, tg = lane & 3;
    const int wm = warp >> 2, wn = warp & 3;

    float acc[4][4][4];
#pragma unroll
    for (int mi = 0; mi < 4; ++mi)
#pragma unroll
        for (int ni = 0; ni < 4; ++ni)
#pragma unroll
            for (int q = 0; q < 4; ++q) acc[mi][ni][q] = 0.f;

    constexpr int KT = H_ / BK;   // 32
    load_tiles(smu, 0, aHi, aLo, bHi, 0, r, cc);
    cp_commit();
    for (int kt = 0; kt < KT; ++kt) {
        cp_wait<0>();
        __syncthreads();
        if (kt + 1 < KT) {
            load_tiles(smu, (kt + 1) & 1, aHi, aLo, bHi, (kt + 1) * BK, r, cc);
            cp_commit();
        }
        const __half* st = sm + (size_t)(kt & 1) * (STAGE_BYTES / 2);
        compute_stage(st, st + PLANE_BYTES / 2, st + PLANE_BYTES, g, tg, wm, wn, acc);
    }

    // epilogue: bias + exact-erf gelu, split-store to compact hmid hi/lo planes
    const float* bf = b_fc + e * I_;
    const size_t base = (size_t)(hoff + tile * BM);
#pragma unroll
    for (int mi = 0; mi < 4; ++mi) {
        const int rr = wm * 64 + mi * 16 + g;
#pragma unroll
        for (int ni = 0; ni < 4; ++ni) {
            const int colg = n0 + wn * 32 + ni * 8 + 2 * tg;
            if (rr < rem) {
                const size_t o = (base + rr) * I_ + colg;
                uint32_t h, l;
                split2h(gelu_f(acc[mi][ni][0] + bf[colg]),
                        gelu_f(acc[mi][ni][1] + bf[colg + 1]), h, l);
                *(uint32_t*)(g_hmidhi + o) = h;
                *(uint32_t*)(g_hmidlo + o) = l;
            }
            if (rr + 8 < rem) {
                const size_t o = (base + rr + 8) * I_ + colg;
                uint32_t h, l;
                split2h(gelu_f(acc[mi][ni][2] + bf[colg]),
                        gelu_f(acc[mi][ni][3] + bf[colg + 1]), h, l);
                *(uint32_t*)(g_hmidhi + o) = h;
                *(uint32_t*)(g_hmidlo + o) = l;
            }
        }
    }
}

// ---------------- k4: grouped GEMM2  out += gate * (hmid @ w_proj^T + b_proj) ----------------
__global__ __launch_bounds__(256, 2)
void gemm_proj_kernel(const float* __restrict__ b_proj, float* __restrict__ out) {
    const int e    = blockIdx.z;
    const int tile = blockIdx.y;
    const int cnt  = g_counts[e];
    if (tile * BM >= cnt) return;
    const int rem  = min(cnt - tile * BM, BM);
    const int hoff = g_offsets[e];
    const int n0   = blockIdx.x * BN;

    extern __shared__ __half sm[];
    __shared__ int   tok_s[BM];
    __shared__ float gate_s[BM];

    const int tid = threadIdx.x;
    if (tid < BM) {
        const int rr  = tile * BM + tid;
        const int idx = e * T_ + min(rr, cnt - 1);
        tok_s[tid]  = g_tok[idx];
        gate_s[tid] = g_gate[idx];
    }
    __syncthreads();

    const int cc = tid & 3;
    const int r  = tid >> 2;
    const __half* aHi[2]; const __half* aLo[2]; const __half* bHi[2];
#pragma unroll
    for (int p = 0; p < 2; ++p) {
        const int row  = r + p * 64;
        const int slot = min(hoff + tile * BM + row, NPAIR - 1);   // clamp OOB tail rows
        const size_t ao = (size_t)slot * I_ + cc * 8;
        const size_t bo = ((size_t)e * H_ + n0 + row) * I_ + cc * 8;
        aHi[p] = g_hmidhi + ao;   aLo[p] = g_hmidlo + ao;
        bHi[p] = g_wprojhi + bo;
    }
    const uint32_t smu = (uint32_t)__cvta_generic_to_shared(sm);

    const int lane = tid & 31, warp = tid >> 5;
    const int g = lane >> 2, tg = lane & 3;
    const int wm = warp >> 2, wn = warp & 3;

    float acc[4][4][4];
#pragma unroll
    for (int mi = 0; mi < 4; ++mi)
#pragma unroll
        for (int ni = 0; ni < 4; ++ni)
#pragma unroll
            for (int q = 0; q < 4; ++q) acc[mi][ni][q] = 0.f;

    constexpr int KT = I_ / BK;   // 64
    load_tiles(smu, 0, aHi, aLo, bHi, 0, r, cc);
    cp_commit();
    for (int kt = 0; kt < KT; ++kt) {
        cp_wait<0>();
        __syncthreads();
        if (kt + 1 < KT) {
            load_tiles(smu, (kt + 1) & 1, aHi, aLo, bHi, (kt + 1) * BK, r, cc);
            cp_commit();
        }
        const __half* st = sm + (size_t)(kt & 1) * (STAGE_BYTES / 2);
        compute_stage(st, st + PLANE_BYTES / 2, st + PLANE_BYTES, g, tg, wm, wn, acc);
    }

    // epilogue: bias, gate scale, scatter-add into out
    const float* bp = b_proj + e * H_;
#pragma unroll
    for (int mi = 0; mi < 4; ++mi) {
        const int rr = wm * 64 + mi * 16 + g;
#pragma unroll
        for (int ni = 0; ni < 4; ++ni) {
            const int colg = n0 + wn * 32 + ni * 8 + 2 * tg;
            if (rr < rem) {
                const int tk = tok_s[rr];
                const float gv = gate_s[rr];
                atomicAdd(out + (size_t)tk * H_ + colg,     gv * (acc[mi][ni][0] + bp[colg]));
                atomicAdd(out + (size_t)tk * H_ + colg + 1, gv * (acc[mi][ni][1] + bp[colg + 1]));
            }
            if (rr + 8 < rem) {
                const int tk = tok_s[rr + 8];
                const float gv = gate_s[rr + 8];
                atomicAdd(out + (size_t)tk * H_ + colg,     gv * (acc[mi][ni][2] + bp[colg]));
                atomicAdd(out + (size_t)tk * H_ + colg + 1, gv * (acc[mi][ni][3] + bp[colg + 1]));
            }
        }
    }
}

// ---------------- launch ----------------
extern "C" void kernel_launch(void* const* d_in, const int* in_sizes, int n_in,
                              void* d_out, int out_size) {
    const float* x      = (const float*)d_in[0];
    const float* w_gate = (const float*)d_in[1];
    const float* w_fc   = (const float*)d_in[2];
    const float* b_fc   = (const float*)d_in[3];
    const float* w_proj = (const float*)d_in[4];
    const float* b_proj = (const float*)d_in[5];
    float* out = (float*)d_out;

    cudaFuncSetAttribute(gemm_fc_kernel,   cudaFuncAttributeMaxDynamicSharedMemorySize, SMEM_TOTAL);
    cudaFuncSetAttribute(gemm_proj_kernel, cudaFuncAttributeMaxDynamicSharedMemorySize, SMEM_TOTAL);

    static uint2* p_xhi = nullptr;
    static uint2* p_xlo, *p_wfchi, *p_wprojhi;
    if (!p_xhi) {
        void* p;
        cudaGetSymbolAddress(&p, g_xhi);     p_xhi     = (uint2*)p;
        cudaGetSymbolAddress(&p, g_xlo);     p_xlo     = (uint2*)p;
        cudaGetSymbolAddress(&p, g_wfchi);   p_wfchi   = (uint2*)p;
        cudaGetSymbolAddress(&p, g_wprojhi); p_wprojhi = (uint2*)p;
    }

    constexpr int SPLIT_BLOCKS = (T_ * H_ + E_ * I_ * H_ + E_ * H_ * I_) / (4 * 256);

    // launch order: split_all(0) route(1) scan(2) gemm_fc(3) gemm_proj(4)
    // -> ncu's fixed capture slot (launch index 3) lands on gemm_fc_kernel.
    split_all_kernel<<<SPLIT_BLOCKS, 256>>>((const float4*)x, (const float4*)w_fc,
                                            (const float4*)w_proj,
                                            p_xhi, p_xlo, p_wfchi, p_wprojhi,
                                            (float4*)out);
    route_kernel<<<T_ / 128, 128>>>(x, w_gate);
    scan_kernel<<<1, 1>>>();
    gemm_fc_kernel<<<dim3(I_ / BN, T_ / BM, E_), 256, SMEM_TOTAL>>>(b_fc);
    gemm_proj_kernel<<<dim3(H_ / BN, T_ / BM, E_), 256, SMEM_TOTAL>>>(b_proj, out);
}